// round 3
// baseline (speedup 1.0000x reference)
#include <cuda_runtime.h>
#include <stdint.h>
#include <math.h>

// Problem constants (TopKGate: x[N,4096] @ W[64,4096]^T, top-2 + softmax + scatter)
#define D_DIM 4096
#define E_DIM 64
#define BM    128          // tokens per CTA
#define BK    16           // k-slice per tile
#define NTHREADS 256
#define XS (BM + 4)        // 132: smem stride for x tile [k][m], keeps b64/float4 alignment
#define WS (E_DIM + 4)     // 68:  smem stride for w tile [k][e]
#define ES (E_DIM + 1)     // 65:  epilogue stride, conflict-free column scan

#define GEMM_FLOATS (2*BK*XS + 2*BK*WS)   // 6400
#define EPI_FLOATS  (BM*ES)               // 8320
#define SMEM_FLOATS (EPI_FLOATS > GEMM_FLOATS ? EPI_FLOATS : GEMM_FLOATS)

__device__ __forceinline__ uint64_t pack2(float lo, float hi) {
    uint64_t r; asm("mov.b64 %0, {%1,%2};" : "=l"(r) : "f"(lo), "f"(hi)); return r;
}
__device__ __forceinline__ void unpack2(uint64_t v, float& lo, float& hi) {
    asm("mov.b64 {%0,%1}, %2;" : "=f"(lo), "=f"(hi) : "l"(v));
}
// Packed fp32 FMA (sm_103a FFMA2) — 2x FFMA throughput, identical rounding to fmaf.
__device__ __forceinline__ uint64_t ffma2(uint64_t a, uint64_t b, uint64_t c) {
    uint64_t d; asm("fma.rn.f32x2 %0, %1, %2, %3;" : "=l"(d) : "l"(a), "l"(b), "l"(c)); return d;
}

__global__ __launch_bounds__(NTHREADS, 1)
void topk_gate_kernel(const float* __restrict__ x, const float* __restrict__ W,
                      float* __restrict__ out, int N, int write_idx) {
    __shared__ __align__(16) float smem[SMEM_FLOATS];
    float* xs = smem;               // [2][BK][XS]
    float* ws = smem + 2*BK*XS;     // [2][BK][WS]

    const int tid  = threadIdx.x;
    const int row0 = blockIdx.x * BM;

    // ---- gmem load mapping: 3x float4 per thread per tile ----
    const int lrow = tid >> 2;          // 0..63
    const int lkc  = (tid & 3) * 4;     // 0,4,8,12
    const float* xg0 = x + (size_t)(row0 + lrow)      * D_DIM + lkc;
    const float* xg1 = x + (size_t)(row0 + lrow + 64) * D_DIM + lkc;
    const float* wg  = W + (size_t)lrow               * D_DIM + lkc;   // lrow = expert id

    // ---- compute mapping: 8 tokens (as 4 b64 pairs) x 4 experts per thread ----
    const int tm0 = (tid & 15) * 8;     // token offset 0..120
    const int tn0 = (tid >> 4) * 4;     // expert offset 0..60

    uint64_t acc[4][4];
    #pragma unroll
    for (int i = 0; i < 4; i++)
        #pragma unroll
        for (int j = 0; j < 4; j++) acc[i][j] = 0ull;

    float4 xr0, xr1, wr;

    // prologue: tile 0 -> buf 0
    xr0 = *(const float4*)(xg0);
    xr1 = *(const float4*)(xg1);
    wr  = *(const float4*)(wg);
    {
        xs[(lkc+0)*XS + lrow] = xr0.x; xs[(lkc+1)*XS + lrow] = xr0.y;
        xs[(lkc+2)*XS + lrow] = xr0.z; xs[(lkc+3)*XS + lrow] = xr0.w;
        xs[(lkc+0)*XS + lrow+64] = xr1.x; xs[(lkc+1)*XS + lrow+64] = xr1.y;
        xs[(lkc+2)*XS + lrow+64] = xr1.z; xs[(lkc+3)*XS + lrow+64] = xr1.w;
        ws[(lkc+0)*WS + lrow] = wr.x; ws[(lkc+1)*WS + lrow] = wr.y;
        ws[(lkc+2)*WS + lrow] = wr.z; ws[(lkc+3)*WS + lrow] = wr.w;
    }
    __syncthreads();

    const int nTiles = D_DIM / BK;      // 256
    for (int t = 0; t < nTiles; ++t) {
        const int cur = t & 1;
        if (t + 1 < nTiles) {           // register-staged prefetch of next tile
            const size_t off = (size_t)(t + 1) * BK;
            xr0 = *(const float4*)(xg0 + off);
            xr1 = *(const float4*)(xg1 + off);
            wr  = *(const float4*)(wg  + off);
        }
        const float* xb = xs + cur * BK * XS;
        const float* wb = ws + cur * BK * WS;
        #pragma unroll
        for (int k = 0; k < BK; k++) {
            // token pairs straight from transposed smem as b64 (no pack needed)
            const uint64_t* xp = (const uint64_t*)(xb + k*XS + tm0);
            const uint64_t a0 = xp[0], a1 = xp[1], a2 = xp[2], a3 = xp[3];
            const float4 wv = *(const float4*)(wb + k*WS + tn0);
            const uint64_t b0 = pack2(wv.x, wv.x), b1 = pack2(wv.y, wv.y);
            const uint64_t b2 = pack2(wv.z, wv.z), b3 = pack2(wv.w, wv.w);
            acc[0][0]=ffma2(a0,b0,acc[0][0]); acc[0][1]=ffma2(a0,b1,acc[0][1]);
            acc[0][2]=ffma2(a0,b2,acc[0][2]); acc[0][3]=ffma2(a0,b3,acc[0][3]);
            acc[1][0]=ffma2(a1,b0,acc[1][0]); acc[1][1]=ffma2(a1,b1,acc[1][1]);
            acc[1][2]=ffma2(a1,b2,acc[1][2]); acc[1][3]=ffma2(a1,b3,acc[1][3]);
            acc[2][0]=ffma2(a2,b0,acc[2][0]); acc[2][1]=ffma2(a2,b1,acc[2][1]);
            acc[2][2]=ffma2(a2,b2,acc[2][2]); acc[2][3]=ffma2(a2,b3,acc[2][3]);
            acc[3][0]=ffma2(a3,b0,acc[3][0]); acc[3][1]=ffma2(a3,b1,acc[3][1]);
            acc[3][2]=ffma2(a3,b2,acc[3][2]); acc[3][3]=ffma2(a3,b3,acc[3][3]);
        }
        if (t + 1 < nTiles) {
            const int nxt = cur ^ 1;
            float* xb2 = xs + nxt * BK * XS;
            float* wb2 = ws + nxt * BK * WS;
            xb2[(lkc+0)*XS + lrow] = xr0.x; xb2[(lkc+1)*XS + lrow] = xr0.y;
            xb2[(lkc+2)*XS + lrow] = xr0.z; xb2[(lkc+3)*XS + lrow] = xr0.w;
            xb2[(lkc+0)*XS + lrow+64] = xr1.x; xb2[(lkc+1)*XS + lrow+64] = xr1.y;
            xb2[(lkc+2)*XS + lrow+64] = xr1.z; xb2[(lkc+3)*XS + lrow+64] = xr1.w;
            wb2[(lkc+0)*WS + lrow] = wr.x; wb2[(lkc+1)*WS + lrow] = wr.y;
            wb2[(lkc+2)*WS + lrow] = wr.z; wb2[(lkc+3)*WS + lrow] = wr.w;
        }
        __syncthreads();   // one barrier per tile: writes went to nxt, reads were from cur
    }

    // ---- epilogue: smem reused as logits tile [BM][ES] ----
    float* slog = smem;   // safe: last loop iteration ended with __syncthreads()
    #pragma unroll
    for (int i = 0; i < 4; i++) {
        #pragma unroll
        for (int j = 0; j < 4; j++) {
            float lo, hi;
            unpack2(acc[i][j], lo, hi);
            slog[(tm0 + 2*i    ) * ES + tn0 + j] = lo;
            slog[(tm0 + 2*i + 1) * ES + tn0 + j] = hi;
        }
    }
    __syncthreads();

    // per-token top-2 (jax tie semantics: strict '>', earliest index wins) + softmax
    float w1 = 0.f, w2 = 0.f; int i1 = 0, i2 = 0;
    if (tid < BM) {
        const float* r = slog + tid * ES;
        float b1 = -3.4e38f, b2 = -3.4e38f; int j1 = 0, j2 = 0;
        #pragma unroll
        for (int e = 0; e < E_DIM; e++) {
            const float v = r[e];
            if (v > b1)      { b2 = b1; j2 = j1; b1 = v; j1 = e; }
            else if (v > b2) { b2 = v; j2 = e; }
        }
        const float e2  = expf(b2 - b1);
        const float inv = 1.0f / (1.0f + e2);
        w1 = inv; w2 = e2 * inv; i1 = j1; i2 = j2;
    }
    __syncthreads();

    // zero the tile collectively (conflict-free: consecutive e per thread)
    for (int i = tid; i < BM * E_DIM; i += NTHREADS)
        slog[(i >> 6) * ES + (i & 63)] = 0.0f;
    __syncthreads();

    if (tid < BM) {
        slog[tid * ES + i1] = w1;
        slog[tid * ES + i2] = w2;
        if (write_idx) {
            float* oi = out + (size_t)N * E_DIM + (size_t)(row0 + tid) * 2;
            oi[0] = (float)i1;
            oi[1] = (float)i2;
        }
    }
    __syncthreads();

    // coalesced writeback of the full weights tile
    for (int i = tid; i < BM * E_DIM; i += NTHREADS)
        out[(size_t)row0 * E_DIM + i] = slog[(i >> 6) * ES + (i & 63)];
}

extern "C" void kernel_launch(void* const* d_in, const int* in_sizes, int n_in,
                              void* d_out, int out_size) {
    const float* x = (const float*)d_in[0];   // [N, 4096]
    const float* W = (const float*)d_in[1];   // [64, 4096]
    float* out = (float*)d_out;

    const int N = in_sizes[0] / D_DIM;        // 16384
    // If the harness concatenates both outputs (weights [N*E] then indices [N*2]
    // cast to float), write indices too; otherwise weights only.
    const int write_idx = (out_size >= N * E_DIM + 2 * N) ? 1 : 0;

    dim3 grid(N / BM);
    topk_gate_kernel<<<grid, NTHREADS>>>(x, W, out, N, write_idx);
}

// round 5
// speedup vs baseline: 1.3237x; 1.3237x over previous
#include <cuda_runtime.h>
#include <stdint.h>
#include <math.h>

// Problem constants (TopKGate: x[N,4096] @ W[64,4096]^T, top-2 + softmax + scatter)
#define D_DIM 4096
#define E_DIM 64
#define BM    128          // tokens per CTA
#define BK    16           // k-slice per tile
#define NTHREADS 256
#define XS (BM + 4)        // 132: smem stride for x tile [k][m], keeps b64 alignment
#define WS (E_DIM + 4)     // 68:  smem stride for w tile [k][e]
#define ES (E_DIM + 1)     // 65:  epilogue stride, conflict-free column scan

#define GEMM_FLOATS (2*BK*XS + 2*BK*WS)   // 6400
#define EPI_FLOATS  (BM*ES)               // 8320
#define SMEM_FLOATS (EPI_FLOATS > GEMM_FLOATS ? EPI_FLOATS : GEMM_FLOATS)

__device__ __forceinline__ uint64_t pack2(float lo, float hi) {
    uint64_t r; asm("mov.b64 %0, {%1,%2};" : "=l"(r) : "f"(lo), "f"(hi)); return r;
}
__device__ __forceinline__ void unpack2(uint64_t v, float& lo, float& hi) {
    asm("mov.b64 {%0,%1}, %2;" : "=f"(lo), "=f"(hi) : "l"(v));
}
// Packed fp32 FMA (sm_103a FFMA2) — 2x FFMA throughput, identical rounding to fmaf.
__device__ __forceinline__ uint64_t ffma2(uint64_t a, uint64_t b, uint64_t c) {
    uint64_t d; asm("fma.rn.f32x2 %0, %1, %2, %3;" : "=l"(d) : "l"(a), "l"(b), "l"(c)); return d;
}

__global__ __launch_bounds__(NTHREADS, 1)
void topk_gate_kernel(const float* __restrict__ x, const float* __restrict__ W,
                      float* __restrict__ out, int N, int write_idx) {
    __shared__ __align__(16) float smem[SMEM_FLOATS];
    float* xs = smem;               // [2][BK][XS]
    float* ws = smem + 2*BK*XS;     // [2][BK][WS]

    const int tid  = threadIdx.x;
    const int row0 = blockIdx.x * BM;

    // ---- gmem load mapping: 3x float4 per thread per tile ----
    const int lrow = tid >> 2;          // 0..63
    const int lkc  = (tid & 3) * 4;     // 0,4,8,12
    const float* xg0 = x + (size_t)(row0 + lrow)      * D_DIM + lkc;
    const float* xg1 = x + (size_t)(row0 + lrow + 64) * D_DIM + lkc;
    const float* wg  = W + (size_t)lrow               * D_DIM + lkc;   // lrow = expert id

    // ---- compute mapping: 8 tokens as 4 INTERLEAVED b64 pairs x 4 experts ----
    // token pairs: {m0, m0+1} + 32*i, i=0..3  -> each LDS.64 phase is one
    // contiguous 128B span across lanes 0..15 => conflict-free (was 4-way).
    const int m0  = (tid & 15) * 2;     // 0,2,..,30
    const int tn0 = (tid >> 4) * 4;     // expert offset 0..60

    uint64_t acc[4][4];
    #pragma unroll
    for (int i = 0; i < 4; i++)
        #pragma unroll
        for (int j = 0; j < 4; j++) acc[i][j] = 0ull;

    float4 xr0, xr1, wr;

    // prologue: tile 0 -> buf 0
    xr0 = *(const float4*)(xg0);
    xr1 = *(const float4*)(xg1);
    wr  = *(const float4*)(wg);
    {
        xs[(lkc+0)*XS + lrow] = xr0.x; xs[(lkc+1)*XS + lrow] = xr0.y;
        xs[(lkc+2)*XS + lrow] = xr0.z; xs[(lkc+3)*XS + lrow] = xr0.w;
        xs[(lkc+0)*XS + lrow+64] = xr1.x; xs[(lkc+1)*XS + lrow+64] = xr1.y;
        xs[(lkc+2)*XS + lrow+64] = xr1.z; xs[(lkc+3)*XS + lrow+64] = xr1.w;
        ws[(lkc+0)*WS + lrow] = wr.x; ws[(lkc+1)*WS + lrow] = wr.y;
        ws[(lkc+2)*WS + lrow] = wr.z; ws[(lkc+3)*WS + lrow] = wr.w;
    }
    __syncthreads();

    const int nTiles = D_DIM / BK;      // 256
    for (int t = 0; t < nTiles; ++t) {
        const int cur = t & 1;
        if (t + 1 < nTiles) {           // register-staged prefetch of next tile
            const size_t off = (size_t)(t + 1) * BK;
            xr0 = *(const float4*)(xg0 + off);
            xr1 = *(const float4*)(xg1 + off);
            wr  = *(const float4*)(wg  + off);
        }
        const float* xb = xs + cur * BK * XS + m0;
        const float* wb = ws + cur * BK * WS + tn0;
        #pragma unroll
        for (int k = 0; k < BK; k++) {
            // interleaved token pairs straight from transposed smem as b64
            const float* xk = xb + k*XS;
            const uint64_t a0 = *(const uint64_t*)(xk);
            const uint64_t a1 = *(const uint64_t*)(xk + 32);
            const uint64_t a2 = *(const uint64_t*)(xk + 64);
            const uint64_t a3 = *(const uint64_t*)(xk + 96);
            const float4 wv = *(const float4*)(wb + k*WS);
            const uint64_t b0 = pack2(wv.x, wv.x), b1 = pack2(wv.y, wv.y);
            const uint64_t b2 = pack2(wv.z, wv.z), b3 = pack2(wv.w, wv.w);
            acc[0][0]=ffma2(a0,b0,acc[0][0]); acc[0][1]=ffma2(a0,b1,acc[0][1]);
            acc[0][2]=ffma2(a0,b2,acc[0][2]); acc[0][3]=ffma2(a0,b3,acc[0][3]);
            acc[1][0]=ffma2(a1,b0,acc[1][0]); acc[1][1]=ffma2(a1,b1,acc[1][1]);
            acc[1][2]=ffma2(a1,b2,acc[1][2]); acc[1][3]=ffma2(a1,b3,acc[1][3]);
            acc[2][0]=ffma2(a2,b0,acc[2][0]); acc[2][1]=ffma2(a2,b1,acc[2][1]);
            acc[2][2]=ffma2(a2,b2,acc[2][2]); acc[2][3]=ffma2(a2,b3,acc[2][3]);
            acc[3][0]=ffma2(a3,b0,acc[3][0]); acc[3][1]=ffma2(a3,b1,acc[3][1]);
            acc[3][2]=ffma2(a3,b2,acc[3][2]); acc[3][3]=ffma2(a3,b3,acc[3][3]);
        }
        if (t + 1 < nTiles) {
            const int nxt = cur ^ 1;
            float* xb2 = xs + nxt * BK * XS;
            float* wb2 = ws + nxt * BK * WS;
            xb2[(lkc+0)*XS + lrow] = xr0.x; xb2[(lkc+1)*XS + lrow] = xr0.y;
            xb2[(lkc+2)*XS + lrow] = xr0.z; xb2[(lkc+3)*XS + lrow] = xr0.w;
            xb2[(lkc+0)*XS + lrow+64] = xr1.x; xb2[(lkc+1)*XS + lrow+64] = xr1.y;
            xb2[(lkc+2)*XS + lrow+64] = xr1.z; xb2[(lkc+3)*XS + lrow+64] = xr1.w;
            wb2[(lkc+0)*WS + lrow] = wr.x; wb2[(lkc+1)*WS + lrow] = wr.y;
            wb2[(lkc+2)*WS + lrow] = wr.z; wb2[(lkc+3)*WS + lrow] = wr.w;
        }
        __syncthreads();   // one barrier per tile: writes went to nxt, reads were from cur
    }

    // ---- epilogue: smem reused as logits tile [BM][ES] ----
    float* slog = smem;   // safe: last loop iteration ended with __syncthreads()
    #pragma unroll
    for (int i = 0; i < 4; i++) {
        #pragma unroll
        for (int j = 0; j < 4; j++) {
            float lo, hi;
            unpack2(acc[i][j], lo, hi);
            slog[(m0 + 32*i    ) * ES + tn0 + j] = lo;
            slog[(m0 + 32*i + 1) * ES + tn0 + j] = hi;
        }
    }
    __syncthreads();

    // per-token top-2 (jax tie semantics: strict '>', earliest index wins) + softmax
    float w1 = 0.f, w2 = 0.f; int i1 = 0, i2 = 0;
    if (tid < BM) {
        const float* r = slog + tid * ES;
        float b1 = -3.4e38f, b2 = -3.4e38f; int j1 = 0, j2 = 0;
        #pragma unroll
        for (int e = 0; e < E_DIM; e++) {
            const float v = r[e];
            if (v > b1)      { b2 = b1; j2 = j1; b1 = v; j1 = e; }
            else if (v > b2) { b2 = v; j2 = e; }
        }
        const float e2  = expf(b2 - b1);
        const float inv = 1.0f / (1.0f + e2);
        w1 = inv; w2 = e2 * inv; i1 = j1; i2 = j2;
    }
    __syncthreads();

    // zero the tile collectively (conflict-free: consecutive e per thread)
    for (int i = tid; i < BM * E_DIM; i += NTHREADS)
        slog[(i >> 6) * ES + (i & 63)] = 0.0f;
    __syncthreads();

    if (tid < BM) {
        slog[tid * ES + i1] = w1;
        slog[tid * ES + i2] = w2;
        if (write_idx) {
            float* oi = out + (size_t)N * E_DIM + (size_t)(row0 + tid) * 2;
            oi[0] = (float)i1;
            oi[1] = (float)i2;
        }
    }
    __syncthreads();

    // coalesced writeback of the full weights tile
    for (int i = tid; i < BM * E_DIM; i += NTHREADS)
        out[(size_t)row0 * E_DIM + i] = slog[(i >> 6) * ES + (i & 63)];
}

extern "C" void kernel_launch(void* const* d_in, const int* in_sizes, int n_in,
                              void* d_out, int out_size) {
    const float* x = (const float*)d_in[0];   // [N, 4096]
    const float* W = (const float*)d_in[1];   // [64, 4096]
    float* out = (float*)d_out;

    const int N = in_sizes[0] / D_DIM;        // 16384
    // If the harness concatenates both outputs (weights [N*E] then indices [N*2]
    // cast to float), write indices too; otherwise weights only.
    const int write_idx = (out_size >= N * E_DIM + 2 * N) ? 1 : 0;

    dim3 grid(N / BM);
    topk_gate_kernel<<<grid, NTHREADS>>>(x, W, out, N, write_idx);
}